// round 1
// baseline (speedup 1.0000x reference)
#include <cuda_runtime.h>

// EGNN layer, B=4, N=512, D=64, H=1.
// Key simplification: hidden width H==1 makes every edge-MLP scalar.
//   a_i = dot(h_i, eW1[0:D]),  b_j = dot(h_j, eW1[D:2D])   (per-node precompute)
//   per edge: s = a_i + b_j + dij*eW1[2D] + eb1
//             mu = (silu(silu(s)*eW2+eb2)*eW3+eb3) * mask_i * mask_j
//             phi = silu(mu*pW1+pb1)*pW2+pb2          (scalar)
//             v   = silu(mu*nW1+nb1)                   (scalar)
//   x_new_i = x_i + sum_j rij[i,j,:]*phi_ij
//   m_node_i = (sum_j v_ij) * nW2 + N*nb2   (D-vector, O(N) not O(N^2))
//   h_new = GRU(m_node, h) * mask

#define BB 4
#define NN 512
#define DD 64

__device__ float g_a [BB * NN];  // dot(h_i, eW1[0:D])
__device__ float g_bb[BB * NN];  // dot(h_j, eW1[D:2D])
__device__ float g_S [BB * NN];  // sum_j v_ij

__device__ __forceinline__ float sigmoid_f(float x) {
    return 1.0f / (1.0f + __expf(-x));
}
__device__ __forceinline__ float silu_f(float x) {
    return x / (1.0f + __expf(-x));
}

// ---------------------------------------------------------------------------
// Kernel 1: per-node projections a_i, b_i.  grid = B*N blocks of 64 threads.
// ---------------------------------------------------------------------------
__global__ void node_proj_kernel(const float* __restrict__ h,
                                 const float* __restrict__ eW1) {
    const int node = blockIdx.x;     // b*N + i
    const int t    = threadIdx.x;    // 0..63
    const float hv = h[node * DD + t];
    float pa = hv * eW1[t];          // eW1 is (2D+1, 1) row-major
    float pb = hv * eW1[DD + t];

    #pragma unroll
    for (int o = 16; o > 0; o >>= 1) {
        pa += __shfl_down_sync(0xffffffffu, pa, o);
        pb += __shfl_down_sync(0xffffffffu, pb, o);
    }
    __shared__ float sa[2], sb[2];
    if ((t & 31) == 0) { sa[t >> 5] = pa; sb[t >> 5] = pb; }
    __syncthreads();
    if (t == 0) {
        g_a [node] = sa[0] + sa[1];
        g_bb[node] = sb[0] + sb[1];
    }
}

// ---------------------------------------------------------------------------
// Kernel 2: edge loop.  grid = B*N blocks (one per destination node i),
// 256 threads sweep j.  Produces x_new and S_i.
// ---------------------------------------------------------------------------
__global__ __launch_bounds__(256) void edge_kernel(
    const float* __restrict__ x,
    const float* __restrict__ rij,
    const float* __restrict__ dij,
    const float* __restrict__ mask,
    const float* __restrict__ eW1, const float* __restrict__ eb1,
    const float* __restrict__ eW2, const float* __restrict__ eb2,
    const float* __restrict__ eW3, const float* __restrict__ eb3,
    const float* __restrict__ pW1, const float* __restrict__ pb1,
    const float* __restrict__ pW2, const float* __restrict__ pb2,
    const float* __restrict__ nW1, const float* __restrict__ nb1,
    float* __restrict__ out)     // x_new written at offset B*N*D
{
    const int node = blockIdx.x;          // b*N + i
    const int b    = node / NN;
    const int tid  = threadIdx.x;

    // H==1 scalar weights
    const float wd    = eW1[2 * DD];
    const float c_eb1 = eb1[0];
    const float c_eW2 = eW2[0], c_eb2 = eb2[0];
    const float c_eW3 = eW3[0], c_eb3 = eb3[0];
    const float c_pW1 = pW1[0], c_pb1 = pb1[0];
    const float c_pW2 = pW2[0], c_pb2 = pb2[0];
    const float c_nW1 = nW1[0], c_nb1 = nb1[0];

    const float ai = g_a[node];
    const float mi = mask[node];

    const float* __restrict__ dptr = dij + (size_t)node * NN;
    const float* __restrict__ rptr = rij + (size_t)node * NN * 3;
    const float* __restrict__ bbp  = g_bb + b * NN;
    const float* __restrict__ mkp  = mask + b * NN;

    float x0 = 0.f, x1 = 0.f, x2 = 0.f, S = 0.f;

    for (int j = tid; j < NN; j += 256) {
        float s  = ai + bbp[j] + dptr[j] * wd + c_eb1;
        float t1 = silu_f(s);
        float u  = silu_f(fmaf(t1, c_eW2, c_eb2));
        float m  = fmaf(u, c_eW3, c_eb3);
        float mu = m * mi * mkp[j];
        float phi = fmaf(silu_f(fmaf(mu, c_pW1, c_pb1)), c_pW2, c_pb2);
        float v   = silu_f(fmaf(mu, c_nW1, c_nb1));
        S += v;
        x0 = fmaf(rptr[3 * j + 0], phi, x0);
        x1 = fmaf(rptr[3 * j + 1], phi, x1);
        x2 = fmaf(rptr[3 * j + 2], phi, x2);
    }

    // block reduce 4 values across 8 warps
    #pragma unroll
    for (int o = 16; o > 0; o >>= 1) {
        x0 += __shfl_down_sync(0xffffffffu, x0, o);
        x1 += __shfl_down_sync(0xffffffffu, x1, o);
        x2 += __shfl_down_sync(0xffffffffu, x2, o);
        S  += __shfl_down_sync(0xffffffffu, S , o);
    }
    __shared__ float red[8][4];
    const int wid = tid >> 5;
    if ((tid & 31) == 0) {
        red[wid][0] = x0; red[wid][1] = x1; red[wid][2] = x2; red[wid][3] = S;
    }
    __syncthreads();
    if (tid == 0) {
        float r0 = 0.f, r1 = 0.f, r2 = 0.f, rs = 0.f;
        #pragma unroll
        for (int w = 0; w < 8; w++) {
            r0 += red[w][0]; r1 += red[w][1]; r2 += red[w][2]; rs += red[w][3];
        }
        g_S[node] = rs;
        float* xo = out + (size_t)BB * NN * DD + (size_t)node * 3;
        xo[0] = x[node * 3 + 0] + r0;
        xo[1] = x[node * 3 + 1] + r1;
        xo[2] = x[node * 3 + 2] + r2;
    }
}

// ---------------------------------------------------------------------------
// Kernel 3: m_node assembly + GRU.  grid = B*N blocks of 64 threads (one per d).
// ---------------------------------------------------------------------------
__global__ __launch_bounds__(64) void gru_kernel(
    const float* __restrict__ h,
    const float* __restrict__ mask,
    const float* __restrict__ nW2, const float* __restrict__ nb2,
    const float* __restrict__ Wih, const float* __restrict__ bih,
    const float* __restrict__ Whh, const float* __restrict__ bhh,
    float* __restrict__ out)
{
    const int node = blockIdx.x;
    const int d    = threadIdx.x;   // 0..63

    __shared__ float mn[DD], hs[DD];
    const float S = g_S[node];
    // m_node[d] = S * nW2[0,d] + N * nb2[d]   (nb2 added once per edge, N edges)
    mn[d] = fmaf(S, nW2[d], (float)NN * nb2[d]);
    hs[d] = h[node * DD + d];
    __syncthreads();

    float ir = bih[d], iz = bih[DD + d], inn = bih[2 * DD + d];
    float hr = bhh[d], hz = bhh[DD + d], hn  = bhh[2 * DD + d];

    const float* __restrict__ Wr = Wih + (size_t)d * DD;
    const float* __restrict__ Wz = Wih + (size_t)(DD + d) * DD;
    const float* __restrict__ Wn = Wih + (size_t)(2 * DD + d) * DD;
    const float* __restrict__ Ur = Whh + (size_t)d * DD;
    const float* __restrict__ Uz = Whh + (size_t)(DD + d) * DD;
    const float* __restrict__ Un = Whh + (size_t)(2 * DD + d) * DD;

    #pragma unroll 8
    for (int k = 0; k < DD; k++) {
        const float m = mn[k], hh = hs[k];
        ir  = fmaf(Wr[k], m,  ir);
        iz  = fmaf(Wz[k], m,  iz);
        inn = fmaf(Wn[k], m,  inn);
        hr  = fmaf(Ur[k], hh, hr);
        hz  = fmaf(Uz[k], hh, hz);
        hn  = fmaf(Un[k], hh, hn);
    }

    const float r = sigmoid_f(ir + hr);
    const float z = sigmoid_f(iz + hz);
    const float n = tanhf(fmaf(r, hn, inn));
    const float hnew = (1.0f - z) * n + z * hs[d];
    out[node * DD + d] = hnew * mask[node];
}

// ---------------------------------------------------------------------------
extern "C" void kernel_launch(void* const* d_in, const int* in_sizes, int n_in,
                              void* d_out, int out_size) {
    const float* h    = (const float*)d_in[0];
    const float* x    = (const float*)d_in[1];
    const float* rij  = (const float*)d_in[2];
    const float* dij  = (const float*)d_in[3];
    const float* mask = (const float*)d_in[4];
    const float* eW1  = (const float*)d_in[5];
    const float* eb1  = (const float*)d_in[6];
    const float* eW2  = (const float*)d_in[7];
    const float* eb2  = (const float*)d_in[8];
    const float* eW3  = (const float*)d_in[9];
    const float* eb3  = (const float*)d_in[10];
    const float* pW1  = (const float*)d_in[11];
    const float* pb1  = (const float*)d_in[12];
    const float* pW2  = (const float*)d_in[13];
    const float* pb2  = (const float*)d_in[14];
    const float* nW1  = (const float*)d_in[15];
    const float* nb1  = (const float*)d_in[16];
    const float* nW2  = (const float*)d_in[17];
    const float* nb2  = (const float*)d_in[18];
    const float* Wih  = (const float*)d_in[19];
    const float* bih  = (const float*)d_in[20];
    const float* Whh  = (const float*)d_in[21];
    const float* bhh  = (const float*)d_in[22];
    float* out = (float*)d_out;

    node_proj_kernel<<<BB * NN, 64>>>(h, eW1);
    edge_kernel<<<BB * NN, 256>>>(x, rij, dij, mask,
                                  eW1, eb1, eW2, eb2, eW3, eb3,
                                  pW1, pb1, pW2, pb2, nW1, nb1, out);
    gru_kernel<<<BB * NN, 64>>>(h, mask, nW2, nb2, Wih, bih, Whh, bhh, out);
}

// round 2
// speedup vs baseline: 1.0002x; 1.0002x over previous
#include <cuda_runtime.h>

// EGNN layer, B=4, N=512, D=64, H=1 — fused, division-free version.
// H==1 collapses all edge MLPs to scalar chains:
//   a_i = dot(h_i, eW1[0:D]),  b_j = dot(h_j, eW1[D:2D])   (node_proj kernel)
//   per edge: scalar chain with 4 silu (tanh.approx based)
//   x_new_i = x_i + sum_j rij[i,j,:]*phi_ij
//   m_node_i = (sum_j v_ij)*nW2 + N*nb2 ;  h_new = GRU(m_node, h) * mask
// GRU fused into the per-node edge block (block owns node i end-to-end).

#define BB 4
#define NN 512
#define DD 64

__device__ float g_a [BB * NN];  // dot(h_i, eW1[0:D])
__device__ float g_bb[BB * NN];  // dot(h_j, eW1[D:2D])

__device__ __forceinline__ float tanh_ap(float x) {
    float y;
    asm("tanh.approx.f32 %0, %1;" : "=f"(y) : "f"(x));
    return y;
}
__device__ __forceinline__ float sigmoid_f(float x) {
    return fmaf(tanh_ap(0.5f * x), 0.5f, 0.5f);
}
__device__ __forceinline__ float silu_f(float x) {
    return x * sigmoid_f(x);
}

// ---------------------------------------------------------------------------
// Kernel 1: per-node projections a_i, b_i.  grid = B*N blocks of 64 threads.
// ---------------------------------------------------------------------------
__global__ void node_proj_kernel(const float* __restrict__ h,
                                 const float* __restrict__ eW1) {
    const int node = blockIdx.x;
    const int t    = threadIdx.x;    // 0..63
    const float hv = h[node * DD + t];
    float pa = hv * eW1[t];          // eW1 is (2D+1, 1)
    float pb = hv * eW1[DD + t];

    #pragma unroll
    for (int o = 16; o > 0; o >>= 1) {
        pa += __shfl_down_sync(0xffffffffu, pa, o);
        pb += __shfl_down_sync(0xffffffffu, pb, o);
    }
    __shared__ float sa[2], sb[2];
    if ((t & 31) == 0) { sa[t >> 5] = pa; sb[t >> 5] = pb; }
    __syncthreads();
    if (t == 0) {
        g_a [node] = sa[0] + sa[1];
        g_bb[node] = sb[0] + sb[1];
    }
}

// ---------------------------------------------------------------------------
// Kernel 2 (fused): edge loop + x_new + GRU for one node i per block.
// 256 threads; thread t handles j = 2t, 2t+1 with float2 loads.
// ---------------------------------------------------------------------------
__global__ __launch_bounds__(256) void edge_gru_kernel(
    const float* __restrict__ h,
    const float* __restrict__ x,
    const float* __restrict__ rij,
    const float* __restrict__ dij,
    const float* __restrict__ mask,
    const float* __restrict__ eW1, const float* __restrict__ eb1,
    const float* __restrict__ eW2, const float* __restrict__ eb2,
    const float* __restrict__ eW3, const float* __restrict__ eb3,
    const float* __restrict__ pW1, const float* __restrict__ pb1,
    const float* __restrict__ pW2, const float* __restrict__ pb2,
    const float* __restrict__ nW1, const float* __restrict__ nb1,
    const float* __restrict__ nW2, const float* __restrict__ nb2,
    const float* __restrict__ Wih, const float* __restrict__ bih,
    const float* __restrict__ Whh, const float* __restrict__ bhh,
    float* __restrict__ out)   // h_new at 0, x_new at B*N*D
{
    const int node = blockIdx.x;          // b*N + i
    const int b    = node / NN;
    const int tid  = threadIdx.x;

    // H==1 scalar weights
    const float wd    = eW1[2 * DD];
    const float c_eb1 = eb1[0];
    const float c_eW2 = eW2[0], c_eb2 = eb2[0];
    const float c_eW3 = eW3[0], c_eb3 = eb3[0];
    const float c_pW1 = pW1[0], c_pb1 = pb1[0];
    const float c_pW2 = pW2[0], c_pb2 = pb2[0];
    const float c_nW1 = nW1[0], c_nb1 = nb1[0];

    const float mi  = mask[node];
    const float aib = g_a[node] + c_eb1;   // fold ai + eb1

    const float2* __restrict__ d2 = (const float2*)(dij + (size_t)node * NN);
    const float2* __restrict__ r2 = (const float2*)(rij + (size_t)node * NN * 3);
    const float2* __restrict__ b2 = (const float2*)(g_bb + b * NN);
    const float2* __restrict__ k2 = (const float2*)(mask + b * NN);

    // --- edge pass: thread tid owns j = 2*tid, 2*tid+1 ---
    const float2 dv = d2[tid];
    const float2 bv = b2[tid];
    const float2 kv = k2[tid];
    const float2 ra = r2[3 * tid + 0];   // rij[j0].x, rij[j0].y
    const float2 rb = r2[3 * tid + 1];   // rij[j0].z, rij[j1].x
    const float2 rc = r2[3 * tid + 2];   // rij[j1].y, rij[j1].z

    float x0, x1, x2, S;
    {
        // edge j0
        float s  = fmaf(dv.x, wd, aib + bv.x);
        float u  = silu_f(fmaf(silu_f(s), c_eW2, c_eb2));
        float mu = fmaf(u, c_eW3, c_eb3) * mi * kv.x;
        float ph = fmaf(silu_f(fmaf(mu, c_pW1, c_pb1)), c_pW2, c_pb2);
        float v  = silu_f(fmaf(mu, c_nW1, c_nb1));
        S  = v;
        x0 = ra.x * ph;
        x1 = ra.y * ph;
        x2 = rb.x * ph;
    }
    {
        // edge j1
        float s  = fmaf(dv.y, wd, aib + bv.y);
        float u  = silu_f(fmaf(silu_f(s), c_eW2, c_eb2));
        float mu = fmaf(u, c_eW3, c_eb3) * mi * kv.y;
        float ph = fmaf(silu_f(fmaf(mu, c_pW1, c_pb1)), c_pW2, c_pb2);
        float v  = silu_f(fmaf(mu, c_nW1, c_nb1));
        S += v;
        x0 = fmaf(rb.y, ph, x0);
        x1 = fmaf(rc.x, ph, x1);
        x2 = fmaf(rc.y, ph, x2);
    }

    // --- block reduce x0,x1,x2,S over 8 warps ---
    #pragma unroll
    for (int o = 16; o > 0; o >>= 1) {
        x0 += __shfl_down_sync(0xffffffffu, x0, o);
        x1 += __shfl_down_sync(0xffffffffu, x1, o);
        x2 += __shfl_down_sync(0xffffffffu, x2, o);
        S  += __shfl_down_sync(0xffffffffu, S , o);
    }
    __shared__ float red[8][4];
    __shared__ float sS;
    __shared__ float mn[DD], hs[DD];
    const int wid = tid >> 5;
    if ((tid & 31) == 0) {
        red[wid][0] = x0; red[wid][1] = x1; red[wid][2] = x2; red[wid][3] = S;
    }
    // stage h into smem while reducing (threads 64..127 idle otherwise)
    if (tid < DD) hs[tid] = h[node * DD + tid];
    __syncthreads();

    if (tid == 0) {
        float r0 = 0.f, r1 = 0.f, r2s = 0.f, rs = 0.f;
        #pragma unroll
        for (int w = 0; w < 8; w++) {
            r0 += red[w][0]; r1 += red[w][1]; r2s += red[w][2]; rs += red[w][3];
        }
        sS = rs;
        float* xo = out + (size_t)BB * NN * DD + (size_t)node * 3;
        xo[0] = x[node * 3 + 0] + r0;
        xo[1] = x[node * 3 + 1] + r1;
        xo[2] = x[node * 3 + 2] + r2s;
    }
    __syncthreads();

    // --- GRU: threads 0..63, one output dim each ---
    if (tid < DD) {
        const int d = tid;
        const float Sv = sS;
        // m_node[d] = S * nW2[d] + N * nb2[d]
        mn[d] = fmaf(Sv, nW2[d], (float)NN * nb2[d]);
    }
    __syncthreads();

    if (tid < DD) {
        const int d = tid;
        float ir = bih[d], iz = bih[DD + d], inn = bih[2 * DD + d];
        float hr = bhh[d], hz = bhh[DD + d], hn  = bhh[2 * DD + d];

        const float* __restrict__ Wr = Wih + (size_t)d * DD;
        const float* __restrict__ Wz = Wih + (size_t)(DD + d) * DD;
        const float* __restrict__ Wn = Wih + (size_t)(2 * DD + d) * DD;
        const float* __restrict__ Ur = Whh + (size_t)d * DD;
        const float* __restrict__ Uz = Whh + (size_t)(DD + d) * DD;
        const float* __restrict__ Un = Whh + (size_t)(2 * DD + d) * DD;

        #pragma unroll 8
        for (int k = 0; k < DD; k++) {
            const float m = mn[k], hh = hs[k];
            ir  = fmaf(Wr[k], m,  ir);
            iz  = fmaf(Wz[k], m,  iz);
            inn = fmaf(Wn[k], m,  inn);
            hr  = fmaf(Ur[k], hh, hr);
            hz  = fmaf(Uz[k], hh, hz);
            hn  = fmaf(Un[k], hh, hn);
        }

        const float r = sigmoid_f(ir + hr);
        const float z = sigmoid_f(iz + hz);
        const float n = tanh_ap(fmaf(r, hn, inn));
        const float hnew = (1.0f - z) * n + z * hs[d];
        out[node * DD + d] = hnew * mi;
    }
}

// ---------------------------------------------------------------------------
extern "C" void kernel_launch(void* const* d_in, const int* in_sizes, int n_in,
                              void* d_out, int out_size) {
    const float* h    = (const float*)d_in[0];
    const float* x    = (const float*)d_in[1];
    const float* rij  = (const float*)d_in[2];
    const float* dij  = (const float*)d_in[3];
    const float* mask = (const float*)d_in[4];
    const float* eW1  = (const float*)d_in[5];
    const float* eb1  = (const float*)d_in[6];
    const float* eW2  = (const float*)d_in[7];
    const float* eb2  = (const float*)d_in[8];
    const float* eW3  = (const float*)d_in[9];
    const float* eb3  = (const float*)d_in[10];
    const float* pW1  = (const float*)d_in[11];
    const float* pb1  = (const float*)d_in[12];
    const float* pW2  = (const float*)d_in[13];
    const float* pb2  = (const float*)d_in[14];
    const float* nW1  = (const float*)d_in[15];
    const float* nb1  = (const float*)d_in[16];
    const float* nW2  = (const float*)d_in[17];
    const float* nb2  = (const float*)d_in[18];
    const float* Wih  = (const float*)d_in[19];
    const float* bih  = (const float*)d_in[20];
    const float* Whh  = (const float*)d_in[21];
    const float* bhh  = (const float*)d_in[22];
    float* out = (float*)d_out;

    node_proj_kernel<<<BB * NN, 64>>>(h, eW1);
    edge_gru_kernel<<<BB * NN, 256>>>(h, x, rij, dij, mask,
                                      eW1, eb1, eW2, eb2, eW3, eb3,
                                      pW1, pb1, pW2, pb2, nW1, nb1,
                                      nW2, nb2, Wih, bih, Whh, bhh, out);
}

// round 6
// speedup vs baseline: 4.9668x; 4.9659x over previous
#include <cuda_runtime.h>

// EGNN layer, B=4, N=512, D=64, H=1.
// Round 3: kill the GRU uncoalesced weight loads (R2 profile: L1=90%, 50M wavefronts).
//  - gi branch is rank-1 in S_i:  m_node = S*nW2 + N*nb2  =>  gi = S*P + Q
//       P = Wih @ nW2,  Q = Wih @ (N*nb2) + bih      (192-vectors, precomputed)
//  - gh branch uses Whh transposed to WhhT[k][r] so lane reads are coalesced.

#define BB 4
#define NN 512
#define DD 64
#define NNODE (BB * NN)

__device__ float g_a   [NNODE];      // dot(h_i, eW1[0:D])
__device__ float g_bb  [NNODE];      // dot(h_j, eW1[D:2D])
__device__ float g_S   [NNODE];      // sum_j v_ij
__device__ float g_WhhT[DD * 3 * DD];// [k][r] transposed Whh (64 x 192)
__device__ float g_P   [3 * DD];
__device__ float g_Q   [3 * DD];

__device__ __forceinline__ float tanh_ap(float x) {
    float y;
    asm("tanh.approx.f32 %0, %1;" : "=f"(y) : "f"(x));
    return y;
}
__device__ __forceinline__ float sigmoid_f(float x) {
    return fmaf(tanh_ap(0.5f * x), 0.5f, 0.5f);
}
__device__ __forceinline__ float silu_f(float x) {
    return x * sigmoid_f(x);
}

// ---------------------------------------------------------------------------
// Kernel 1: prep.  Blocks 0..511: node projections (4 nodes per block).
//                  Block 512: Whh transpose + P/Q precompute.
// ---------------------------------------------------------------------------
__global__ __launch_bounds__(256) void prep_kernel(
    const float* __restrict__ h,   const float* __restrict__ eW1,
    const float* __restrict__ nW2, const float* __restrict__ nb2,
    const float* __restrict__ Wih, const float* __restrict__ bih,
    const float* __restrict__ Whh)
{
    const int tid = threadIdx.x;
    if (blockIdx.x < NNODE / 4) {
        const int g    = tid >> 6;           // node group 0..3
        const int t    = tid & 63;           // dim 0..63
        const int node = blockIdx.x * 4 + g;
        const float hv = h[node * DD + t];
        float pa = hv * eW1[t];
        float pb = hv * eW1[DD + t];
        #pragma unroll
        for (int o = 16; o > 0; o >>= 1) {
            pa += __shfl_down_sync(0xffffffffu, pa, o);
            pb += __shfl_down_sync(0xffffffffu, pb, o);
        }
        __shared__ float sa[8], sb[8];
        const int w = tid >> 5;
        if ((tid & 31) == 0) { sa[w] = pa; sb[w] = pb; }
        __syncthreads();
        if (t == 0) {
            g_a [node] = sa[2 * g] + sa[2 * g + 1];
            g_bb[node] = sb[2 * g] + sb[2 * g + 1];
        }
    } else {
        // transpose Whh (192x64 -> 64x192); reads coalesced, tiny scatter
        for (int idx = tid; idx < 3 * DD * DD; idx += 256) {
            const int r = idx >> 6;      // 0..191
            const int k = idx & 63;
            g_WhhT[k * (3 * DD) + r] = Whh[idx];
        }
        // P, Q: 192 outputs
        if (tid < 3 * DD) {
            const float* __restrict__ Wr = Wih + (size_t)tid * DD;
            float p = 0.f, q = 0.f;
            #pragma unroll 8
            for (int k = 0; k < DD; k++) {
                p = fmaf(Wr[k], nW2[k], p);
                q = fmaf(Wr[k], (float)NN * nb2[k], q);
            }
            g_P[tid] = p;
            g_Q[tid] = q + bih[tid];
        }
    }
}

// ---------------------------------------------------------------------------
// Kernel 2: edge loop.  One node i per block, 256 threads, 2 edges/thread.
// Produces x_new (at out + B*N*D) and g_S.
// ---------------------------------------------------------------------------
__global__ __launch_bounds__(256) void edge_kernel(
    const float* __restrict__ x,
    const float* __restrict__ rij,
    const float* __restrict__ dij,
    const float* __restrict__ mask,
    const float* __restrict__ eW1, const float* __restrict__ eb1,
    const float* __restrict__ eW2, const float* __restrict__ eb2,
    const float* __restrict__ eW3, const float* __restrict__ eb3,
    const float* __restrict__ pW1, const float* __restrict__ pb1,
    const float* __restrict__ pW2, const float* __restrict__ pb2,
    const float* __restrict__ nW1, const float* __restrict__ nb1,
    float* __restrict__ out)
{
    const int node = blockIdx.x;
    const int b    = node / NN;
    const int tid  = threadIdx.x;

    const float wd    = eW1[2 * DD];
    const float c_eb1 = eb1[0];
    const float c_eW2 = eW2[0], c_eb2 = eb2[0];
    const float c_eW3 = eW3[0], c_eb3 = eb3[0];
    const float c_pW1 = pW1[0], c_pb1 = pb1[0];
    const float c_pW2 = pW2[0], c_pb2 = pb2[0];
    const float c_nW1 = nW1[0], c_nb1 = nb1[0];

    const float mi  = mask[node];
    const float aib = g_a[node] + c_eb1;

    const float2* __restrict__ d2 = (const float2*)(dij + (size_t)node * NN);
    const float2* __restrict__ r2 = (const float2*)(rij + (size_t)node * NN * 3);
    const float2* __restrict__ b2 = (const float2*)(g_bb + b * NN);
    const float2* __restrict__ k2 = (const float2*)(mask + b * NN);

    const float2 dv = d2[tid];
    const float2 bv = b2[tid];
    const float2 kv = k2[tid];
    const float2 ra = r2[3 * tid + 0];
    const float2 rb = r2[3 * tid + 1];
    const float2 rc = r2[3 * tid + 2];

    float x0, x1, x2, S;
    {
        float s  = fmaf(dv.x, wd, aib + bv.x);
        float u  = silu_f(fmaf(silu_f(s), c_eW2, c_eb2));
        float mu = fmaf(u, c_eW3, c_eb3) * mi * kv.x;
        float ph = fmaf(silu_f(fmaf(mu, c_pW1, c_pb1)), c_pW2, c_pb2);
        S  = silu_f(fmaf(mu, c_nW1, c_nb1));
        x0 = ra.x * ph;
        x1 = ra.y * ph;
        x2 = rb.x * ph;
    }
    {
        float s  = fmaf(dv.y, wd, aib + bv.y);
        float u  = silu_f(fmaf(silu_f(s), c_eW2, c_eb2));
        float mu = fmaf(u, c_eW3, c_eb3) * mi * kv.y;
        float ph = fmaf(silu_f(fmaf(mu, c_pW1, c_pb1)), c_pW2, c_pb2);
        S += silu_f(fmaf(mu, c_nW1, c_nb1));
        x0 = fmaf(rb.y, ph, x0);
        x1 = fmaf(rc.x, ph, x1);
        x2 = fmaf(rc.y, ph, x2);
    }

    #pragma unroll
    for (int o = 16; o > 0; o >>= 1) {
        x0 += __shfl_down_sync(0xffffffffu, x0, o);
        x1 += __shfl_down_sync(0xffffffffu, x1, o);
        x2 += __shfl_down_sync(0xffffffffu, x2, o);
        S  += __shfl_down_sync(0xffffffffu, S , o);
    }
    __shared__ float red[8][4];
    const int wid = tid >> 5;
    if ((tid & 31) == 0) {
        red[wid][0] = x0; red[wid][1] = x1; red[wid][2] = x2; red[wid][3] = S;
    }
    __syncthreads();
    if (tid == 0) {
        float r0 = 0.f, r1 = 0.f, r2s = 0.f, rs = 0.f;
        #pragma unroll
        for (int w = 0; w < 8; w++) {
            r0 += red[w][0]; r1 += red[w][1]; r2s += red[w][2]; rs += red[w][3];
        }
        g_S[node] = rs;
        float* xo = out + (size_t)NNODE * DD + (size_t)node * 3;
        xo[0] = x[node * 3 + 0] + r0;
        xo[1] = x[node * 3 + 1] + r1;
        xo[2] = x[node * 3 + 2] + r2s;
    }
}

// ---------------------------------------------------------------------------
// Kernel 3: GRU.  4 nodes per block (64 threads each).  Weight reads are from
// g_WhhT with consecutive-lane addresses (coalesced, L1-resident across groups).
// ---------------------------------------------------------------------------
__global__ __launch_bounds__(256) void gru_kernel(
    const float* __restrict__ h,
    const float* __restrict__ mask,
    const float* __restrict__ bhh,
    float* __restrict__ out)
{
    const int g    = threadIdx.x >> 6;
    const int d    = threadIdx.x & 63;
    const int node = blockIdx.x * 4 + g;

    __shared__ float hs[4][DD];
    hs[g][d] = h[node * DD + d];
    __syncthreads();

    const float S = g_S[node];

    float hr = bhh[d], hz = bhh[DD + d], hn = bhh[2 * DD + d];
    const float* __restrict__ WT = g_WhhT;
    #pragma unroll 8
    for (int k = 0; k < DD; k++) {
        const float hh = hs[g][k];
        hr = fmaf(WT[k * (3 * DD) + d],          hh, hr);
        hz = fmaf(WT[k * (3 * DD) + DD + d],     hh, hz);
        hn = fmaf(WT[k * (3 * DD) + 2 * DD + d], hh, hn);
    }

    const float ir  = fmaf(S, g_P[d],          g_Q[d]);
    const float iz  = fmaf(S, g_P[DD + d],     g_Q[DD + d]);
    const float inn = fmaf(S, g_P[2 * DD + d], g_Q[2 * DD + d]);

    const float r = sigmoid_f(ir + hr);
    const float z = sigmoid_f(iz + hz);
    const float n = tanh_ap(fmaf(r, hn, inn));
    const float hnew = (1.0f - z) * n + z * hs[g][d];
    out[node * DD + d] = hnew * mask[node];
}

// ---------------------------------------------------------------------------
extern "C" void kernel_launch(void* const* d_in, const int* in_sizes, int n_in,
                              void* d_out, int out_size) {
    const float* h    = (const float*)d_in[0];
    const float* x    = (const float*)d_in[1];
    const float* rij  = (const float*)d_in[2];
    const float* dij  = (const float*)d_in[3];
    const float* mask = (const float*)d_in[4];
    const float* eW1  = (const float*)d_in[5];
    const float* eb1  = (const float*)d_in[6];
    const float* eW2  = (const float*)d_in[7];
    const float* eb2  = (const float*)d_in[8];
    const float* eW3  = (const float*)d_in[9];
    const float* eb3  = (const float*)d_in[10];
    const float* pW1  = (const float*)d_in[11];
    const float* pb1  = (const float*)d_in[12];
    const float* pW2  = (const float*)d_in[13];
    const float* pb2  = (const float*)d_in[14];
    const float* nW1  = (const float*)d_in[15];
    const float* nb1  = (const float*)d_in[16];
    const float* nW2  = (const float*)d_in[17];
    const float* nb2  = (const float*)d_in[18];
    const float* Wih  = (const float*)d_in[19];
    const float* bih  = (const float*)d_in[20];
    const float* Whh  = (const float*)d_in[21];
    const float* bhh  = (const float*)d_in[22];
    float* out = (float*)d_out;

    prep_kernel<<<NNODE / 4 + 1, 256>>>(h, eW1, nW2, nb2, Wih, bih, Whh);
    edge_kernel<<<NNODE, 256>>>(x, rij, dij, mask,
                                eW1, eb1, eW2, eb2, eW3, eb3,
                                pW1, pb1, pW2, pb2, nW1, nb1, out);
    gru_kernel<<<NNODE / 4, 256>>>(h, mask, bhh, out);
}

// round 8
// speedup vs baseline: 9.8412x; 1.9814x over previous
#include <cuda_runtime.h>

// EGNN layer, B=4, N=512, D=64, H=1.
// R7: eliminate the prep straggler block (R6 profile: prep=23us, one block doing
// serial uncoalesced transpose + P/Q while 512 blocks idle).
//  - transpose spread over 48 blocks, coalesced writes
//  - P/Q: one warp per output row, coalesced Wih reads + shfl reduce

#define BB 4
#define NN 512
#define DD 64
#define NNODE (BB * NN)

#define NPROJ_BLOCKS (NNODE / 4)        // 512
#define TRANS_BLOCKS 48                 // 12288 elems / 256
#define PQ_BLOCKS    24                 // 192 warps -> 192 outputs

__device__ float g_a   [NNODE];
__device__ float g_bb  [NNODE];
__device__ float g_S   [NNODE];
__device__ float g_WhhT[DD * 3 * DD];   // [k][r]  (64 x 192)
__device__ float g_P   [3 * DD];
__device__ float g_Q   [3 * DD];

__device__ __forceinline__ float tanh_ap(float x) {
    float y;
    asm("tanh.approx.f32 %0, %1;" : "=f"(y) : "f"(x));
    return y;
}
__device__ __forceinline__ float sigmoid_f(float x) {
    return fmaf(tanh_ap(0.5f * x), 0.5f, 0.5f);
}
__device__ __forceinline__ float silu_f(float x) {
    return x * sigmoid_f(x);
}

// ---------------------------------------------------------------------------
// Kernel 1: prep.
//   blocks [0, 512): node projections a_i, b_i (4 nodes per block)
//   blocks [512, 560): Whh transpose, coalesced writes
//   blocks [560, 584): P/Q, one warp per output row
// ---------------------------------------------------------------------------
__global__ __launch_bounds__(256) void prep_kernel(
    const float* __restrict__ h,   const float* __restrict__ eW1,
    const float* __restrict__ nW2, const float* __restrict__ nb2,
    const float* __restrict__ Wih, const float* __restrict__ bih,
    const float* __restrict__ Whh)
{
    const int tid = threadIdx.x;
    const int bid = blockIdx.x;

    if (bid < NPROJ_BLOCKS) {
        const int g    = tid >> 6;
        const int t    = tid & 63;
        const int node = bid * 4 + g;
        const float hv = h[node * DD + t];
        float pa = hv * eW1[t];
        float pb = hv * eW1[DD + t];
        #pragma unroll
        for (int o = 16; o > 0; o >>= 1) {
            pa += __shfl_down_sync(0xffffffffu, pa, o);
            pb += __shfl_down_sync(0xffffffffu, pb, o);
        }
        __shared__ float sa[8], sb[8];
        const int w = tid >> 5;
        if ((tid & 31) == 0) { sa[w] = pa; sb[w] = pb; }
        __syncthreads();
        if (t == 0) {
            g_a [node] = sa[2 * g] + sa[2 * g + 1];
            g_bb[node] = sb[2 * g] + sb[2 * g + 1];
        }
    } else if (bid < NPROJ_BLOCKS + TRANS_BLOCKS) {
        // transpose: thread -> output element (coalesced write)
        const int o = (bid - NPROJ_BLOCKS) * 256 + tid;   // o = k*192 + r
        const int k = o / (3 * DD);
        const int r = o - k * (3 * DD);
        g_WhhT[o] = Whh[r * DD + k];
    } else {
        // P/Q: warp per output row r
        const int warp = (bid - NPROJ_BLOCKS - TRANS_BLOCKS) * 8 + (tid >> 5);
        const int lane = tid & 31;
        if (warp < 3 * DD) {
            const float* __restrict__ Wr = Wih + (size_t)warp * DD;
            const float w0 = Wr[lane], w1 = Wr[32 + lane];
            float p = fmaf(w1, nW2[32 + lane], w0 * nW2[lane]);
            float q = fmaf(w1, (float)NN * nb2[32 + lane],
                           w0 * ((float)NN * nb2[lane]));
            #pragma unroll
            for (int o = 16; o > 0; o >>= 1) {
                p += __shfl_down_sync(0xffffffffu, p, o);
                q += __shfl_down_sync(0xffffffffu, q, o);
            }
            if (lane == 0) {
                g_P[warp] = p;
                g_Q[warp] = q + bih[warp];
            }
        }
    }
}

// ---------------------------------------------------------------------------
// Kernel 2: edge loop.  One node i per block, 256 threads, 2 edges/thread.
// ---------------------------------------------------------------------------
__global__ __launch_bounds__(256) void edge_kernel(
    const float* __restrict__ x,
    const float* __restrict__ rij,
    const float* __restrict__ dij,
    const float* __restrict__ mask,
    const float* __restrict__ eW1, const float* __restrict__ eb1,
    const float* __restrict__ eW2, const float* __restrict__ eb2,
    const float* __restrict__ eW3, const float* __restrict__ eb3,
    const float* __restrict__ pW1, const float* __restrict__ pb1,
    const float* __restrict__ pW2, const float* __restrict__ pb2,
    const float* __restrict__ nW1, const float* __restrict__ nb1,
    float* __restrict__ out)
{
    const int node = blockIdx.x;
    const int b    = node / NN;
    const int tid  = threadIdx.x;

    const float wd    = eW1[2 * DD];
    const float c_eb1 = eb1[0];
    const float c_eW2 = eW2[0], c_eb2 = eb2[0];
    const float c_eW3 = eW3[0], c_eb3 = eb3[0];
    const float c_pW1 = pW1[0], c_pb1 = pb1[0];
    const float c_pW2 = pW2[0], c_pb2 = pb2[0];
    const float c_nW1 = nW1[0], c_nb1 = nb1[0];

    const float mi  = mask[node];
    const float aib = g_a[node] + c_eb1;

    const float2* __restrict__ d2 = (const float2*)(dij + (size_t)node * NN);
    const float2* __restrict__ r2 = (const float2*)(rij + (size_t)node * NN * 3);
    const float2* __restrict__ b2 = (const float2*)(g_bb + b * NN);
    const float2* __restrict__ k2 = (const float2*)(mask + b * NN);

    const float2 dv = d2[tid];
    const float2 bv = b2[tid];
    const float2 kv = k2[tid];
    const float2 ra = r2[3 * tid + 0];
    const float2 rb = r2[3 * tid + 1];
    const float2 rc = r2[3 * tid + 2];

    float x0, x1, x2, S;
    {
        float s  = fmaf(dv.x, wd, aib + bv.x);
        float u  = silu_f(fmaf(silu_f(s), c_eW2, c_eb2));
        float mu = fmaf(u, c_eW3, c_eb3) * mi * kv.x;
        float ph = fmaf(silu_f(fmaf(mu, c_pW1, c_pb1)), c_pW2, c_pb2);
        S  = silu_f(fmaf(mu, c_nW1, c_nb1));
        x0 = ra.x * ph;
        x1 = ra.y * ph;
        x2 = rb.x * ph;
    }
    {
        float s  = fmaf(dv.y, wd, aib + bv.y);
        float u  = silu_f(fmaf(silu_f(s), c_eW2, c_eb2));
        float mu = fmaf(u, c_eW3, c_eb3) * mi * kv.y;
        float ph = fmaf(silu_f(fmaf(mu, c_pW1, c_pb1)), c_pW2, c_pb2);
        S += silu_f(fmaf(mu, c_nW1, c_nb1));
        x0 = fmaf(rb.y, ph, x0);
        x1 = fmaf(rc.x, ph, x1);
        x2 = fmaf(rc.y, ph, x2);
    }

    #pragma unroll
    for (int o = 16; o > 0; o >>= 1) {
        x0 += __shfl_down_sync(0xffffffffu, x0, o);
        x1 += __shfl_down_sync(0xffffffffu, x1, o);
        x2 += __shfl_down_sync(0xffffffffu, x2, o);
        S  += __shfl_down_sync(0xffffffffu, S , o);
    }
    __shared__ float red[8][4];
    const int wid = tid >> 5;
    if ((tid & 31) == 0) {
        red[wid][0] = x0; red[wid][1] = x1; red[wid][2] = x2; red[wid][3] = S;
    }
    __syncthreads();
    if (tid == 0) {
        float r0 = 0.f, r1 = 0.f, r2s = 0.f, rs = 0.f;
        #pragma unroll
        for (int w = 0; w < 8; w++) {
            r0 += red[w][0]; r1 += red[w][1]; r2s += red[w][2]; rs += red[w][3];
        }
        g_S[node] = rs;
        float* xo = out + (size_t)NNODE * DD + (size_t)node * 3;
        xo[0] = x[node * 3 + 0] + r0;
        xo[1] = x[node * 3 + 1] + r1;
        xo[2] = x[node * 3 + 2] + r2s;
    }
}

// ---------------------------------------------------------------------------
// Kernel 3: GRU.  4 nodes per block; WhhT reads coalesced + cached.
// ---------------------------------------------------------------------------
__global__ __launch_bounds__(256) void gru_kernel(
    const float* __restrict__ h,
    const float* __restrict__ mask,
    const float* __restrict__ bhh,
    float* __restrict__ out)
{
    const int g    = threadIdx.x >> 6;
    const int d    = threadIdx.x & 63;
    const int node = blockIdx.x * 4 + g;

    __shared__ float hs[4][DD];
    hs[g][d] = h[node * DD + d];
    __syncthreads();

    const float S = g_S[node];

    float hr = bhh[d], hz = bhh[DD + d], hn = bhh[2 * DD + d];
    const float* __restrict__ WT = g_WhhT;
    #pragma unroll 8
    for (int k = 0; k < DD; k++) {
        const float hh = hs[g][k];
        hr = fmaf(WT[k * (3 * DD) + d],          hh, hr);
        hz = fmaf(WT[k * (3 * DD) + DD + d],     hh, hz);
        hn = fmaf(WT[k * (3 * DD) + 2 * DD + d], hh, hn);
    }

    const float ir  = fmaf(S, g_P[d],          g_Q[d]);
    const float iz  = fmaf(S, g_P[DD + d],     g_Q[DD + d]);
    const float inn = fmaf(S, g_P[2 * DD + d], g_Q[2 * DD + d]);

    const float r = sigmoid_f(ir + hr);
    const float z = sigmoid_f(iz + hz);
    const float n = tanh_ap(fmaf(r, hn, inn));
    const float hnew = (1.0f - z) * n + z * hs[g][d];
    out[node * DD + d] = hnew * mask[node];
}

// ---------------------------------------------------------------------------
extern "C" void kernel_launch(void* const* d_in, const int* in_sizes, int n_in,
                              void* d_out, int out_size) {
    const float* h    = (const float*)d_in[0];
    const float* x    = (const float*)d_in[1];
    const float* rij  = (const float*)d_in[2];
    const float* dij  = (const float*)d_in[3];
    const float* mask = (const float*)d_in[4];
    const float* eW1  = (const float*)d_in[5];
    const float* eb1  = (const float*)d_in[6];
    const float* eW2  = (const float*)d_in[7];
    const float* eb2  = (const float*)d_in[8];
    const float* eW3  = (const float*)d_in[9];
    const float* eb3  = (const float*)d_in[10];
    const float* pW1  = (const float*)d_in[11];
    const float* pb1  = (const float*)d_in[12];
    const float* pW2  = (const float*)d_in[13];
    const float* pb2  = (const float*)d_in[14];
    const float* nW1  = (const float*)d_in[15];
    const float* nb1  = (const float*)d_in[16];
    const float* nW2  = (const float*)d_in[17];
    const float* nb2  = (const float*)d_in[18];
    const float* Wih  = (const float*)d_in[19];
    const float* bih  = (const float*)d_in[20];
    const float* Whh  = (const float*)d_in[21];
    const float* bhh  = (const float*)d_in[22];
    float* out = (float*)d_out;

    prep_kernel<<<NPROJ_BLOCKS + TRANS_BLOCKS + PQ_BLOCKS, 256>>>(
        h, eW1, nW2, nb2, Wih, bih, Whh);
    edge_kernel<<<NNODE, 256>>>(x, rij, dij, mask,
                                eW1, eb1, eW2, eb2, eW3, eb3,
                                pW1, pb1, pW2, pb2, nW1, nb1, out);
    gru_kernel<<<NNODE / 4, 256>>>(h, mask, bhh, out);
}